// round 15
// baseline (speedup 1.0000x reference)
#include <cuda_runtime.h>
#include <cuda_fp16.h>
#include <math.h>
#include <stdint.h>

typedef __half fp16;

#define Bsz   1024
#define Hsz   512
#define INsz  256
#define OUTsz 256
#define Tsz   128
#define K0T   768
#define K1T   1024
#define KFT   512
#define KLT   256

#define LDSW  72                      // smem row stride (elems), 64 data + 8 pad
#define TILEB (128 * LDSW * 2)        // 18432 B per fp16 tile
#define SLOTB (2 * TILEB)             // 36864 B per pipeline stage (A, W)
#define NSTG  4
#define SMEMSZ (1024 + NSTG * SLOTB)  // 148480 B (4-stage)
#define SMF_STRIDE 132                // fp32 staging row stride
#define NTHR 512
#define GRIDC 128

// ---------------- persistent device buffers ----------------
__device__ __align__(256) fp16  g_x0[2][Bsz * K0T];
__device__ __align__(256) fp16  g_x1[2][Bsz * K1T];
__device__ __align__(256) float g_c[2][Bsz * Hsz];
__device__ __align__(256) fp16  g_zs[Tsz * Bsz * INsz];
__device__ __align__(256) fp16  g_W0[2048 * K0T];
__device__ __align__(256) fp16  g_W1[2048 * K1T];
__device__ __align__(256) fp16  g_Wf[INsz * KFT];
__device__ __align__(256) fp16  g_Wl[OUTsz * KLT];
__device__ __align__(256) float g_b0[2048];
__device__ __align__(256) float g_b1[2048];
__device__ __align__(256) float g_bfc[INsz];
__device__ __align__(256) float g_bln[OUTsz];
__device__ unsigned g_count;          // grid barrier counter (reset each launch)

// ---------------- helpers ----------------
__device__ __forceinline__ uint32_t smem_u32(const void* p) {
    uint32_t a;
    asm("{ .reg .u64 t; cvta.to.shared.u64 t, %1; cvt.u32.u64 %0, t; }" : "=r"(a) : "l"(p));
    return a;
}
__device__ __forceinline__ void cpa16(uint32_t s, const void* g) {
    asm volatile("cp.async.cg.shared.global [%0], [%1], 16;" :: "r"(s), "l"(g));
}
__device__ __forceinline__ void ldsm_x4(uint32_t* r, uint32_t a) {
    asm volatile("ldmatrix.sync.aligned.m8n8.x4.shared.b16 {%0,%1,%2,%3}, [%4];"
                 : "=r"(r[0]), "=r"(r[1]), "=r"(r[2]), "=r"(r[3]) : "r"(a));
}
__device__ __forceinline__ void ldsm_x2(uint32_t* r, uint32_t a) {
    asm volatile("ldmatrix.sync.aligned.m8n8.x2.shared.b16 {%0,%1}, [%2];"
                 : "=r"(r[0]), "=r"(r[1]) : "r"(a));
}
__device__ __forceinline__ void mma16816(float* c, const uint32_t* a, const uint32_t* b) {
    asm volatile(
        "mma.sync.aligned.m16n8k16.row.col.f32.f16.f16.f32 "
        "{%0,%1,%2,%3}, {%4,%5,%6,%7}, {%8,%9}, {%0,%1,%2,%3};"
        : "+f"(c[0]), "+f"(c[1]), "+f"(c[2]), "+f"(c[3])
        : "r"(a[0]), "r"(a[1]), "r"(a[2]), "r"(a[3]), "r"(b[0]), "r"(b[1]));
}
// Fast, overflow-safe transcendentals (validated in R14: rel_err unchanged)
__device__ __forceinline__ float fsig(float x) {
    return __fdividef(1.f, 1.f + __expf(-x));
}
__device__ __forceinline__ float ftanh(float x) {
    return 1.f - __fdividef(2.f, 1.f + __expf(2.f * x));
}
__device__ __forceinline__ uint32_t pk2(fp16 a, fp16 b) {
    return (uint32_t)__half_as_ushort(a) | ((uint32_t)__half_as_ushort(b) << 16);
}
template<int N>
__device__ __forceinline__ void zero_acc(float* a) {
    #pragma unroll
    for (int i = 0; i < N; i++) a[i] = 0.f;
}

// Software grid barrier. Cross-CTA data: writers use STG (reaches L2), readers
// use cp.async.cg (L2); __threadfence orders STG before the arrival.
__device__ __forceinline__ void gridbar(unsigned target) {
    __threadfence();
    __syncthreads();
    if (threadIdx.x == 0) {
        atomicAdd(&g_count, 1u);
        while (((volatile unsigned*)&g_count)[0] < target) __nanosleep(64);
    }
    __syncthreads();
}

// ---------------- single-pass fp16 GEMM, caller-owned acc ----------------
// acc layout: [MF][NF][4] flattened; MF=MTILE/64, NF=NTILE/32.
// KCH=64, 4-stage cp.async pipeline, single __syncthreads per chunk.
template<int MTILE, int NTILE>
__device__ __forceinline__ void gemm_k(
    char* smem, float* acc,
    const fp16* __restrict__ A, int lda, int aoff, int m0,
    const fp16* __restrict__ W, int ldw, int n0,
    int kbeg, int kend)
{
    constexpr int MF = MTILE / 64;
    constexpr int NF = NTILE / 32;
    constexpr int WMR = MTILE / 4, WNR = NTILE / 4;

    const uint32_t sb = smem_u32(smem);
    const int tid = threadIdx.x;
    const int wid = tid >> 5, lane = tid & 31;
    const int wn = wid & 3, wm = wid >> 2;

    const uint32_t a_off = ((wm * WMR + (lane & 15)) * LDSW + (lane >> 4) * 8) * 2;
    uint32_t b_off;
    if constexpr (NF >= 2)
        b_off = ((wn * WNR + ((lane >> 4) << 3) + (lane & 7)) * LDSW
                 + ((lane >> 3) & 1) * 8) * 2;
    else
        b_off = ((wn * WNR + (lane & 7)) * LDSW + ((lane >> 3) & 1) * 8) * 2;

    const int lrow = tid >> 3;          // 0..63
    const int lk   = (tid & 7) * 8;     // elem offset
    const int nch  = (kend - kbeg) / 64;

    auto load_chunk = [&](int ch, int slot) {
        const uint32_t base = sb + 1024 + slot * SLOTB;
        const int k0 = kbeg + ch * 64;
        #pragma unroll
        for (int s = 0; s < MTILE / 64; s++) {
            const int r = lrow + s * 64;
            const uint32_t so = base + (r * LDSW + lk) * 2;
            cpa16(so, A + (size_t)(m0 + r) * lda + aoff + k0 + lk);
        }
        if constexpr (NTILE >= 64) {
            #pragma unroll
            for (int s = 0; s < NTILE / 64; s++) {
                const int r = lrow + s * 64;
                const uint32_t so = base + TILEB + (r * LDSW + lk) * 2;
                cpa16(so, W + (size_t)(n0 + r) * ldw + k0 + lk);
            }
        } else {
            if (lrow < NTILE) {
                const uint32_t so = base + TILEB + (lrow * LDSW + lk) * 2;
                cpa16(so, W + (size_t)(n0 + lrow) * ldw + k0 + lk);
            }
        }
        asm volatile("cp.async.commit_group;");
    };

    load_chunk(0, 0);
    if (nch > 1) load_chunk(1, 1);
    if (nch > 2) load_chunk(2, 2);

    for (int ch = 0; ch < nch; ch++) {
        if (ch + 2 < nch)      asm volatile("cp.async.wait_group 2;");
        else if (ch + 1 < nch) asm volatile("cp.async.wait_group 1;");
        else                   asm volatile("cp.async.wait_group 0;");
        __syncthreads();
        if (ch + 3 < nch) load_chunk(ch + 3, (ch + 3) & (NSTG - 1));

        const uint32_t base = sb + 1024 + (ch & (NSTG - 1)) * SLOTB;
        const uint32_t aba = base + a_off;
        const uint32_t bbw = base + TILEB + b_off;

        #pragma unroll
        for (int ks = 0; ks < 4; ks++) {
            uint32_t A4[MF][4];
            #pragma unroll
            for (int mi = 0; mi < MF; mi++)
                ldsm_x4(A4[mi], aba + mi * 16 * LDSW * 2 + ks * 32);
            if constexpr (NF >= 2) {
                uint32_t W4[NF / 2][4];
                #pragma unroll
                for (int n2 = 0; n2 < NF / 2; n2++)
                    ldsm_x4(W4[n2], bbw + n2 * 16 * LDSW * 2 + ks * 32);
                #pragma unroll
                for (int mi = 0; mi < MF; mi++)
                    #pragma unroll
                    for (int ni = 0; ni < NF; ni++)
                        mma16816(acc + (mi * NF + ni) * 4, A4[mi], &W4[ni >> 1][(ni & 1) * 2]);
            } else {
                uint32_t W2[2];
                ldsm_x2(W2, bbw + ks * 32);
                #pragma unroll
                for (int mi = 0; mi < MF; mi++)
                    mma16816(acc + mi * 4, A4[mi], W2);
            }
        }
    }
}

// Stage acc to fp32 smem (+1024, SMF_STRIDE floats/row).
template<int MTILE, int NTILE>
__device__ __forceinline__ void stage_acc(char* smem, const float* acc)
{
    __syncthreads();
    const int tid = threadIdx.x;
    const int wid = tid >> 5, lane = tid & 31;
    const int wn = wid & 3, wm = wid >> 2;
    constexpr int WMR = MTILE / 4, WNR = NTILE / 4;
    constexpr int MF = MTILE / 64, NF = NTILE / 32;
    float* smf = (float*)(smem + 1024);
    #pragma unroll
    for (int mi = 0; mi < MF; mi++) {
        const int m = wm * WMR + mi * 16 + (lane >> 2);
        #pragma unroll
        for (int ni = 0; ni < NF; ni++) {
            const int n = wn * WNR + ni * 8 + (lane & 3) * 2;
            const float* a = acc + (mi * NF + ni) * 4;
            *(float2*)&smf[m * SMF_STRIDE + n]       = make_float2(a[0], a[1]);
            *(float2*)&smf[(m + 8) * SMF_STRIDE + n] = make_float2(a[2], a[3]);
        }
    }
    __syncthreads();
}

// ---------------- LSTM epilogue (128x128 tile) ----------------
__device__ __forceinline__ void lstm_epilogue(
    char* smem, int m0, int n0, float* __restrict__ cst,
    fp16* __restrict__ d1, int ld1, int off1,
    fp16* __restrict__ d2, int ld2, int off2)
{
    const int tid = threadIdx.x;
    const float* sbias = (const float*)smem;
    const float* smf = (const float*)(smem + 1024);
    const int hb = n0 >> 2;

    #pragma unroll
    for (int it = 0; it < 8; it++) {
        const int idx = it * NTHR + tid;
        const int bl = idx >> 5, hl = idx & 31;
        float4 g = *(const float4*)&smf[bl * SMF_STRIDE + hl * 4];
        const float gi = g.x + sbias[hl * 4 + 0];
        const float gf = g.y + sbias[hl * 4 + 1];
        const float gg = g.z + sbias[hl * 4 + 2];
        const float go = g.w + sbias[hl * 4 + 3];
        const size_t ci = (size_t)(m0 + bl) * Hsz + hb + hl;
        const float cc = fsig(gf) * cst[ci] + fsig(gi) * ftanh(gg);
        cst[ci] = cc;
        const fp16 hn = __float2half(fsig(go) * ftanh(cc));
        d1[(size_t)(m0 + bl) * ld1 + off1 + hb + hl] = hn;
        if (d2) d2[(size_t)(m0 + bl) * ld2 + off2 + hb + hl] = hn;
    }
    __syncthreads();
}

// ---------------- FC epilogue (64x32 tile, one float4 per thread) ----------------
__device__ __forceinline__ void fc_epilogue(
    char* smem, int m0, int n0,
    fp16* __restrict__ d1, int ld1,
    fp16* __restrict__ zs)
{
    const int tid = threadIdx.x;
    const float* sbias = (const float*)smem;
    const float* smf = (const float*)(smem + 1024);

    const int bl = tid >> 3;            // 0..63
    const int nq = (tid & 7) * 4;       // 0..28
    float4 v = *(const float4*)&smf[bl * SMF_STRIDE + nq];
    v.x += sbias[nq + 0]; v.y += sbias[nq + 1];
    v.z += sbias[nq + 2]; v.w += sbias[nq + 3];
    const uint2 vh = make_uint2(pk2(__float2half(v.x), __float2half(v.y)),
                                pk2(__float2half(v.z), __float2half(v.w)));
    *(uint2*)(d1 + (size_t)(m0 + bl) * ld1 + n0 + nq) = vh;
    *(uint2*)(zs + (size_t)(m0 + bl) * INsz + n0 + nq) = vh;
    __syncthreads();
}

// ---------------- persistent decoder ----------------
__global__ void __launch_bounds__(NTHR, 1) decoder_persistent()
{
    extern __shared__ char smem[];
    const int cta = blockIdx.x;
    const int tid = threadIdx.x;
    const int m0L = (cta & 7) * 128, n0L = (cta >> 3) * 128;
    const int m0F = (cta & 15) * 64, n0F = (cta >> 4) * 32;
    unsigned gen = 0;

    float acc[32];

    for (int t = 0; t < Tsz; t++) {
        const int p = t & 1, pn = p ^ 1;

        // ---- P1: L0 full (k 0..768) + epilogue
        if (tid < 128) ((float*)smem)[tid] = g_b0[n0L + tid];
        zero_acc<32>(acc);
        gemm_k<128, 128>(smem, acc, g_x0[p], K0T, 0, m0L,
                         g_W0, K0T, n0L, 0, K0T);
        stage_acc<128, 128>(smem, acc);
        lstm_epilogue(smem, m0L, n0L, g_c[0],
                      g_x1[p], K1T, 0,
                      g_x0[pn], K0T, 256);
        gridbar(++gen * GRIDC);

        // ---- P2: L1 full (k 0..1024) + epilogue
        if (tid < 128) ((float*)smem)[tid] = g_b1[n0L + tid];
        zero_acc<32>(acc);
        gemm_k<128, 128>(smem, acc, g_x1[p], K1T, 0, m0L,
                         g_W1, K1T, n0L, 0, 1024);
        stage_acc<128, 128>(smem, acc);
        lstm_epilogue(smem, m0L, n0L, g_c[1],
                      g_x1[pn], K1T, 512,
                      nullptr, 0, 0);
        gridbar(++gen * GRIDC);

        // ---- P3: fc (all 128 CTAs, 64x32 tiles)
        if (tid < 32) ((float*)smem)[tid] = g_bfc[n0F + tid];
        zero_acc<4>(acc);
        gemm_k<64, 32>(smem, acc, g_x1[pn], K1T, 512, m0F,
                       g_Wf, KFT, n0F, 0, 512);
        stage_acc<64, 32>(smem, acc);
        fc_epilogue(smem, m0F, n0F,
                    g_x0[pn], K0T,
                    g_zs + (size_t)t * Bsz * INsz);
        gridbar(++gen * GRIDC);
    }
}

// ---------------- final linear kernel ----------------
__global__ void __launch_bounds__(NTHR, 1)
lin_kernel(const fp16* __restrict__ A, int lda,
           const fp16* __restrict__ W, int Ktot,
           const float* __restrict__ bias,
           float* __restrict__ fout, int ldo)
{
    extern __shared__ char smem[];
    const int tid = threadIdx.x;
    const int m0 = blockIdx.x * 128;
    const int n0 = blockIdx.y * 128;

    if (tid < 128) ((float*)smem)[tid] = bias[n0 + tid];

    float acc[32];
    zero_acc<32>(acc);
    gemm_k<128, 128>(smem, acc, A, lda, 0, m0, W, Ktot, n0, 0, Ktot);
    stage_acc<128, 128>(smem, acc);

    const float* sbias = (const float*)smem;
    const float* smf = (const float*)(smem + 1024);

    #pragma unroll
    for (int it = 0; it < 8; it++) {
        const int idx = it * NTHR + tid;
        const int bl = idx >> 5;
        const int nq = (idx & 31) * 4;
        float4 v = *(const float4*)&smf[bl * SMF_STRIDE + nq];
        v.x += sbias[nq + 0]; v.y += sbias[nq + 1];
        v.z += sbias[nq + 2]; v.w += sbias[nq + 3];
        *(float4*)&fout[(size_t)(m0 + bl) * ldo + n0 + nq] = v;
    }
}

// ---------------- single fused prologue (packs + state init + barrier reset) ----------------
__global__ void prologue_kernel(
    const float* __restrict__ z0, const float* __restrict__ h0, const float* __restrict__ c0,
    const float* __restrict__ Wih0, const float* __restrict__ Whh0,
    const float* __restrict__ bih0, const float* __restrict__ bhh0,
    const float* __restrict__ Wih1, const float* __restrict__ Whh1,
    const float* __restrict__ bih1, const float* __restrict__ bhh1,
    const float* __restrict__ fcW, const float* __restrict__ fcb,
    const float* __restrict__ linW, const float* __restrict__ linb)
{
    const size_t stride = (size_t)gridDim.x * blockDim.x;
    const size_t t0 = (size_t)blockIdx.x * blockDim.x + threadIdx.x;

    if (t0 == 0) g_count = 0;   // reset grid barrier each launch/replay

    for (size_t idx = t0; idx < (size_t)2048 * K0T; idx += stride) {
        int rr = (int)(idx / K0T), k = (int)(idx - (size_t)rr * K0T);
        int h = rr >> 2, g = rr & 3;
        int orow = g * Hsz + h;
        float v = (k < INsz) ? Wih0[(size_t)orow * INsz + k]
                             : Whh0[(size_t)orow * Hsz + (k - INsz)];
        g_W0[idx] = __float2half(v);
    }
    for (size_t idx = t0; idx < (size_t)2048 * K1T; idx += stride) {
        int rr = (int)(idx / K1T), k = (int)(idx - (size_t)rr * K1T);
        int h = rr >> 2, g = rr & 3;
        int orow = g * Hsz + h;
        float v = (k < Hsz) ? Wih1[(size_t)orow * Hsz + k]
                            : Whh1[(size_t)orow * Hsz + (k - Hsz)];
        g_W1[idx] = __float2half(v);
    }
    for (size_t idx = t0; idx < (size_t)INsz * KFT; idx += stride)
        g_Wf[idx] = __float2half(fcW[idx]);
    for (size_t idx = t0; idx < (size_t)OUTsz * KLT; idx += stride)
        g_Wl[idx] = __float2half(linW[idx]);
    for (size_t t = t0; t < 2048; t += stride) {
        int h = (int)(t >> 2), g = (int)(t & 3);
        int orow = g * Hsz + h;
        g_b0[t] = bih0[orow] + bhh0[orow];
        g_b1[t] = bih1[orow] + bhh1[orow];
    }
    for (size_t t = t0; t < INsz; t += stride) g_bfc[t] = fcb[t];
    for (size_t t = t0; t < OUTsz; t += stride) g_bln[t] = linb[t];
    const size_t BH = (size_t)Bsz * Hsz;
    for (size_t i = t0; i < BH; i += stride) {
        int b = (int)(i >> 9), h = (int)(i & 511);
        g_x0[0][(size_t)b * K0T + 256 + h] = __float2half(h0[i]);
        g_x1[0][(size_t)b * K1T + 512 + h] = __float2half(h0[BH + i]);
        g_c[0][i] = c0[i];
        g_c[1][i] = c0[BH + i];
    }
    for (size_t i = t0; i < (size_t)Bsz * INsz; i += stride) {
        int b = (int)(i >> 8), z = (int)(i & 255);
        g_x0[0][(size_t)b * K0T + z] = __float2half(z0[i]);
    }
}

// ---------------- host ----------------
extern "C" void kernel_launch(void* const* d_in, const int* in_sizes, int n_in,
                              void* d_out, int out_size)
{
    const float* z0   = (const float*)d_in[0];
    const float* h0   = (const float*)d_in[1];
    const float* c0   = (const float*)d_in[2];
    const float* Wih0 = (const float*)d_in[3];
    const float* Whh0 = (const float*)d_in[4];
    const float* bih0 = (const float*)d_in[5];
    const float* bhh0 = (const float*)d_in[6];
    const float* Wih1 = (const float*)d_in[7];
    const float* Whh1 = (const float*)d_in[8];
    const float* bih1 = (const float*)d_in[9];
    const float* bhh1 = (const float*)d_in[10];
    const float* fcW  = (const float*)d_in[11];
    const float* fcb  = (const float*)d_in[12];
    const float* linW = (const float*)d_in[13];
    const float* linb = (const float*)d_in[14];

    fp16 *zs, *Wl;
    float *bln;
    cudaGetSymbolAddress((void**)&zs,  g_zs);
    cudaGetSymbolAddress((void**)&Wl,  g_Wl);
    cudaGetSymbolAddress((void**)&bln, g_bln);

    cudaFuncSetAttribute(decoder_persistent,
                         cudaFuncAttributeMaxDynamicSharedMemorySize, SMEMSZ);
    cudaFuncSetAttribute(lin_kernel,
                         cudaFuncAttributeMaxDynamicSharedMemorySize, SMEMSZ);

    prologue_kernel<<<2048, 256>>>(z0, h0, c0, Wih0, Whh0, bih0, bhh0,
                                   Wih1, Whh1, bih1, bhh1, fcW, fcb, linW, linb);

    decoder_persistent<<<GRIDC, NTHR, SMEMSZ>>>();

    dim3 gfin((Tsz * Bsz) / 128, OUTsz / 128);  // (1024, 2)
    lin_kernel<<<gfin, NTHR, SMEMSZ>>>(
        zs, INsz, Wl, KLT, bln, (float*)d_out, OUTsz);
}

// round 17
// speedup vs baseline: 1.0565x; 1.0565x over previous
#include <cuda_runtime.h>
#include <cuda_fp16.h>
#include <math.h>
#include <stdint.h>

typedef __half fp16;

#define Bsz   1024
#define Hsz   512
#define INsz  256
#define OUTsz 256
#define Tsz   128
#define K0T   768
#define K1T   1024
#define KFT   512
#define KLT   256

#define LDSW  72                      // smem row stride (elems), 64 data + 8 pad
#define TILEB (128 * LDSW * 2)        // 18432 B per fp16 tile
#define SLOTB (2 * TILEB)             // 36864 B per pipeline stage (A, W)
#define NSTG  3
#define SMF_STRIDE 132                // fp32 staging row stride
#define SMOFF (1024 + 128 * SMF_STRIDE * 4)   // 68608: slots start after bias+smf
#define SMEMSZ (SMOFF + NSTG * SLOTB)         // 179200 B
#define NTHR 512
#define GRIDC 128

// ---------------- persistent device buffers ----------------
__device__ __align__(256) fp16  g_x0[2][Bsz * K0T];
__device__ __align__(256) fp16  g_x1[2][Bsz * K1T];
__device__ __align__(256) float g_c[2][Bsz * Hsz];
__device__ __align__(256) fp16  g_zs[Tsz * Bsz * INsz];
__device__ __align__(256) fp16  g_W0[2048 * K0T];
__device__ __align__(256) fp16  g_W1[2048 * K1T];
__device__ __align__(256) fp16  g_Wf[INsz * KFT];
__device__ __align__(256) fp16  g_Wl[OUTsz * KLT];
__device__ __align__(256) float g_b0[2048];
__device__ __align__(256) float g_b1[2048];
__device__ __align__(256) float g_bfc[INsz];
__device__ __align__(256) float g_bln[OUTsz];
__device__ __align__(256) unsigned g_cnt[8 * 32];   // per-m-group barrier counters (128B apart)

// ---------------- helpers ----------------
__device__ __forceinline__ uint32_t smem_u32(const void* p) {
    uint32_t a;
    asm("{ .reg .u64 t; cvta.to.shared.u64 t, %1; cvt.u32.u64 %0, t; }" : "=r"(a) : "l"(p));
    return a;
}
__device__ __forceinline__ void cpa16(uint32_t s, const void* g) {
    asm volatile("cp.async.cg.shared.global [%0], [%1], 16;" :: "r"(s), "l"(g));
}
__device__ __forceinline__ void ldsm_x4(uint32_t* r, uint32_t a) {
    asm volatile("ldmatrix.sync.aligned.m8n8.x4.shared.b16 {%0,%1,%2,%3}, [%4];"
                 : "=r"(r[0]), "=r"(r[1]), "=r"(r[2]), "=r"(r[3]) : "r"(a));
}
__device__ __forceinline__ void ldsm_x2(uint32_t* r, uint32_t a) {
    asm volatile("ldmatrix.sync.aligned.m8n8.x2.shared.b16 {%0,%1}, [%2];"
                 : "=r"(r[0]), "=r"(r[1]) : "r"(a));
}
__device__ __forceinline__ void mma16816(float* c, const uint32_t* a, const uint32_t* b) {
    asm volatile(
        "mma.sync.aligned.m16n8k16.row.col.f32.f16.f16.f32 "
        "{%0,%1,%2,%3}, {%4,%5,%6,%7}, {%8,%9}, {%0,%1,%2,%3};"
        : "+f"(c[0]), "+f"(c[1]), "+f"(c[2]), "+f"(c[3])
        : "r"(a[0]), "r"(a[1]), "r"(a[2]), "r"(a[3]), "r"(b[0]), "r"(b[1]));
}
// libm transcendentals (R13-validated; fast-math variants measured SLOWER on sm_103a)
__device__ __forceinline__ float sigf(float x) { return 1.f / (1.f + expf(-x)); }
__device__ __forceinline__ uint32_t pk2(fp16 a, fp16 b) {
    return (uint32_t)__half_as_ushort(a) | ((uint32_t)__half_as_ushort(b) << 16);
}
template<int N>
__device__ __forceinline__ void zero_acc(float* a) {
    #pragma unroll
    for (int i = 0; i < N; i++) a[i] = 0.f;
}

// Per-m-group barrier (16 CTAs). Writers STG + threadfence before arrival;
// readers use cp.async.cg (L2) after observing the counter.
__device__ __forceinline__ void gridbar_g(int grp, unsigned target) {
    __threadfence();
    __syncthreads();
    if (threadIdx.x == 0) {
        atomicAdd(&g_cnt[grp * 32], 1u);
        while (((volatile unsigned*)&g_cnt[grp * 32])[0] < target) __nanosleep(32);
    }
    __syncthreads();
}

// ---------------- single-pass fp16 GEMM, caller-owned acc ----------------
// acc layout: [MF][NF][4] flattened; MF=MTILE/64, NF=NTILE/32.
// KCH=64, 3-stage cp.async pipeline, single __syncthreads per chunk.
template<int MTILE, int NTILE>
__device__ __forceinline__ void gemm_k(
    char* smem, float* acc,
    const fp16* __restrict__ A, int lda, int aoff, int m0,
    const fp16* __restrict__ W, int ldw, int n0,
    int kbeg, int kend)
{
    constexpr int MF = MTILE / 64;
    constexpr int NF = NTILE / 32;
    constexpr int WMR = MTILE / 4, WNR = NTILE / 4;

    const uint32_t sb = smem_u32(smem);
    const int tid = threadIdx.x;
    const int wid = tid >> 5, lane = tid & 31;
    const int wn = wid & 3, wm = wid >> 2;

    const uint32_t a_off = ((wm * WMR + (lane & 15)) * LDSW + (lane >> 4) * 8) * 2;
    uint32_t b_off;
    if constexpr (NF >= 2)
        b_off = ((wn * WNR + ((lane >> 4) << 3) + (lane & 7)) * LDSW
                 + ((lane >> 3) & 1) * 8) * 2;
    else
        b_off = ((wn * WNR + (lane & 7)) * LDSW + ((lane >> 3) & 1) * 8) * 2;

    const int lrow = tid >> 3;          // 0..63
    const int lk   = (tid & 7) * 8;     // elem offset
    const int nch  = (kend - kbeg) / 64;

    auto load_chunk = [&](int ch, int slot) {
        const uint32_t base = sb + SMOFF + slot * SLOTB;
        const int k0 = kbeg + ch * 64;
        #pragma unroll
        for (int s = 0; s < MTILE / 64; s++) {
            const int r = lrow + s * 64;
            const uint32_t so = base + (r * LDSW + lk) * 2;
            cpa16(so, A + (size_t)(m0 + r) * lda + aoff + k0 + lk);
        }
        if constexpr (NTILE >= 64) {
            #pragma unroll
            for (int s = 0; s < NTILE / 64; s++) {
                const int r = lrow + s * 64;
                const uint32_t so = base + TILEB + (r * LDSW + lk) * 2;
                cpa16(so, W + (size_t)(n0 + r) * ldw + k0 + lk);
            }
        } else {
            if (lrow < NTILE) {
                const uint32_t so = base + TILEB + (lrow * LDSW + lk) * 2;
                cpa16(so, W + (size_t)(n0 + lrow) * ldw + k0 + lk);
            }
        }
        asm volatile("cp.async.commit_group;");
    };

    load_chunk(0, 0);
    if (nch > 1) load_chunk(1, 1);

    for (int ch = 0; ch < nch; ch++) {
        if (ch + 1 < nch) asm volatile("cp.async.wait_group 1;");
        else              asm volatile("cp.async.wait_group 0;");
        __syncthreads();
        if (ch + 2 < nch) load_chunk(ch + 2, (ch + 2) % 3);

        const uint32_t base = sb + SMOFF + (ch % 3) * SLOTB;
        const uint32_t aba = base + a_off;
        const uint32_t bbw = base + TILEB + b_off;

        #pragma unroll
        for (int ks = 0; ks < 4; ks++) {
            uint32_t A4[MF][4];
            #pragma unroll
            for (int mi = 0; mi < MF; mi++)
                ldsm_x4(A4[mi], aba + mi * 16 * LDSW * 2 + ks * 32);
            if constexpr (NF >= 2) {
                uint32_t W4[NF / 2][4];
                #pragma unroll
                for (int n2 = 0; n2 < NF / 2; n2++)
                    ldsm_x4(W4[n2], bbw + n2 * 16 * LDSW * 2 + ks * 32);
                #pragma unroll
                for (int mi = 0; mi < MF; mi++)
                    #pragma unroll
                    for (int ni = 0; ni < NF; ni++)
                        mma16816(acc + (mi * NF + ni) * 4, A4[mi], &W4[ni >> 1][(ni & 1) * 2]);
            } else {
                uint32_t W2[2];
                ldsm_x2(W2, bbw + ks * 32);
                #pragma unroll
                for (int mi = 0; mi < MF; mi++)
                    mma16816(acc + mi * 4, A4[mi], W2);
            }
        }
    }
}

// Stage acc to fp32 smem (+1024, SMF_STRIDE floats/row). smf region is disjoint
// from pipeline slots -> no leading sync needed; trailing sync before reads.
template<int MTILE, int NTILE>
__device__ __forceinline__ void stage_acc(char* smem, const float* acc)
{
    const int tid = threadIdx.x;
    const int wid = tid >> 5, lane = tid & 31;
    const int wn = wid & 3, wm = wid >> 2;
    constexpr int WMR = MTILE / 4, WNR = NTILE / 4;
    constexpr int MF = MTILE / 64, NF = NTILE / 32;
    float* smf = (float*)(smem + 1024);
    #pragma unroll
    for (int mi = 0; mi < MF; mi++) {
        const int m = wm * WMR + mi * 16 + (lane >> 2);
        #pragma unroll
        for (int ni = 0; ni < NF; ni++) {
            const int n = wn * WNR + ni * 8 + (lane & 3) * 2;
            const float* a = acc + (mi * NF + ni) * 4;
            *(float2*)&smf[m * SMF_STRIDE + n]       = make_float2(a[0], a[1]);
            *(float2*)&smf[(m + 8) * SMF_STRIDE + n] = make_float2(a[2], a[3]);
        }
    }
    __syncthreads();
}

// ---------------- LSTM epilogue (128x128 tile) ----------------
__device__ __forceinline__ void lstm_epilogue(
    char* smem, int m0, int n0, float* __restrict__ cst,
    fp16* __restrict__ d1, int ld1, int off1,
    fp16* __restrict__ d2, int ld2, int off2)
{
    const int tid = threadIdx.x;
    const float* sbias = (const float*)smem;
    const float* smf = (const float*)(smem + 1024);
    const int hb = n0 >> 2;

    #pragma unroll
    for (int it = 0; it < 8; it++) {
        const int idx = it * NTHR + tid;
        const int bl = idx >> 5, hl = idx & 31;
        float4 g = *(const float4*)&smf[bl * SMF_STRIDE + hl * 4];
        const float gi = g.x + sbias[hl * 4 + 0];
        const float gf = g.y + sbias[hl * 4 + 1];
        const float gg = g.z + sbias[hl * 4 + 2];
        const float go = g.w + sbias[hl * 4 + 3];
        const size_t ci = (size_t)(m0 + bl) * Hsz + hb + hl;
        const float cc = sigf(gf) * cst[ci] + sigf(gi) * tanhf(gg);
        cst[ci] = cc;
        const fp16 hn = __float2half(sigf(go) * tanhf(cc));
        d1[(size_t)(m0 + bl) * ld1 + off1 + hb + hl] = hn;
        if (d2) d2[(size_t)(m0 + bl) * ld2 + off2 + hb + hl] = hn;
    }
    // no trailing sync: the following group barrier syncs the CTA
}

// ---------------- FC epilogue (64x32 tile, one float4 per thread) ----------------
__device__ __forceinline__ void fc_epilogue(
    char* smem, int m0, int n0,
    fp16* __restrict__ d1, int ld1,
    fp16* __restrict__ zs)
{
    const int tid = threadIdx.x;
    const float* sbias = (const float*)smem;
    const float* smf = (const float*)(smem + 1024);

    const int bl = tid >> 3;            // 0..63
    const int nq = (tid & 7) * 4;       // 0..28
    float4 v = *(const float4*)&smf[bl * SMF_STRIDE + nq];
    v.x += sbias[nq + 0]; v.y += sbias[nq + 1];
    v.z += sbias[nq + 2]; v.w += sbias[nq + 3];
    const uint2 vh = make_uint2(pk2(__float2half(v.x), __float2half(v.y)),
                                pk2(__float2half(v.z), __float2half(v.w)));
    *(uint2*)(d1 + (size_t)(m0 + bl) * ld1 + n0 + nq) = vh;
    *(uint2*)(zs + (size_t)(m0 + bl) * INsz + n0 + nq) = vh;
}

// ---------------- persistent decoder (8 independent m-group pipelines) ----------------
__global__ void __launch_bounds__(NTHR, 1) decoder_persistent()
{
    extern __shared__ char smem[];
    const int cta = blockIdx.x;
    const int tid = threadIdx.x;
    const int grp = cta & 7;            // m-group: batches [grp*128, grp*128+128)
    const int lid = cta >> 3;           // 0..15 within group
    const int m0L = grp * 128, n0L = lid * 128;
    const int m0F = grp * 128 + (lid & 1) * 64;   // fc: group-local 64x32 tiles
    const int n0F = (lid >> 1) * 32;
    unsigned gen = 0;

    float acc[32];

    for (int t = 0; t < Tsz; t++) {
        const int p = t & 1, pn = p ^ 1;

        // ---- P1: L0 full (k 0..768) + epilogue
        if (tid < 128) ((float*)smem)[tid] = g_b0[n0L + tid];
        zero_acc<32>(acc);
        gemm_k<128, 128>(smem, acc, g_x0[p], K0T, 0, m0L,
                         g_W0, K0T, n0L, 0, K0T);
        stage_acc<128, 128>(smem, acc);
        lstm_epilogue(smem, m0L, n0L, g_c[0],
                      g_x1[p], K1T, 0,
                      g_x0[pn], K0T, 256);
        gridbar_g(grp, (++gen) * 16);

        // ---- P2: L1 full (k 0..1024) + epilogue
        if (tid < 128) ((float*)smem)[tid] = g_b1[n0L + tid];
        zero_acc<32>(acc);
        gemm_k<128, 128>(smem, acc, g_x1[p], K1T, 0, m0L,
                         g_W1, K1T, n0L, 0, 1024);
        stage_acc<128, 128>(smem, acc);
        lstm_epilogue(smem, m0L, n0L, g_c[1],
                      g_x1[pn], K1T, 512,
                      nullptr, 0, 0);
        gridbar_g(grp, (++gen) * 16);

        // ---- P3: fc (group-local 64x32 tiles)
        if (tid < 32) ((float*)smem)[tid] = g_bfc[n0F + tid];
        zero_acc<4>(acc);
        gemm_k<64, 32>(smem, acc, g_x1[pn], K1T, 512, m0F,
                       g_Wf, KFT, n0F, 0, 512);
        stage_acc<64, 32>(smem, acc);
        fc_epilogue(smem, m0F, n0F,
                    g_x0[pn], K0T,
                    g_zs + (size_t)t * Bsz * INsz);
        gridbar_g(grp, (++gen) * 16);
    }
}

// ---------------- final linear kernel ----------------
__global__ void __launch_bounds__(NTHR, 1)
lin_kernel(const fp16* __restrict__ A, int lda,
           const fp16* __restrict__ W, int Ktot,
           const float* __restrict__ bias,
           float* __restrict__ fout, int ldo)
{
    extern __shared__ char smem[];
    const int tid = threadIdx.x;
    const int m0 = blockIdx.x * 128;
    const int n0 = blockIdx.y * 128;

    if (tid < 128) ((float*)smem)[tid] = bias[n0 + tid];

    float acc[32];
    zero_acc<32>(acc);
    gemm_k<128, 128>(smem, acc, A, lda, 0, m0, W, Ktot, n0, 0, Ktot);
    stage_acc<128, 128>(smem, acc);

    const float* sbias = (const float*)smem;
    const float* smf = (const float*)(smem + 1024);

    #pragma unroll
    for (int it = 0; it < 8; it++) {
        const int idx = it * NTHR + tid;
        const int bl = idx >> 5;
        const int nq = (idx & 31) * 4;
        float4 v = *(const float4*)&smf[bl * SMF_STRIDE + nq];
        v.x += sbias[nq + 0]; v.y += sbias[nq + 1];
        v.z += sbias[nq + 2]; v.w += sbias[nq + 3];
        *(float4*)&fout[(size_t)(m0 + bl) * ldo + n0 + nq] = v;
    }
}

// ---------------- single fused prologue (packs + state init + barrier reset) ----------------
__global__ void prologue_kernel(
    const float* __restrict__ z0, const float* __restrict__ h0, const float* __restrict__ c0,
    const float* __restrict__ Wih0, const float* __restrict__ Whh0,
    const float* __restrict__ bih0, const float* __restrict__ bhh0,
    const float* __restrict__ Wih1, const float* __restrict__ Whh1,
    const float* __restrict__ bih1, const float* __restrict__ bhh1,
    const float* __restrict__ fcW, const float* __restrict__ fcb,
    const float* __restrict__ linW, const float* __restrict__ linb)
{
    const size_t stride = (size_t)gridDim.x * blockDim.x;
    const size_t t0 = (size_t)blockIdx.x * blockDim.x + threadIdx.x;

    if (t0 < 8 * 32) g_cnt[t0] = 0;   // reset group barriers each launch/replay

    for (size_t idx = t0; idx < (size_t)2048 * K0T; idx += stride) {
        int rr = (int)(idx / K0T), k = (int)(idx - (size_t)rr * K0T);
        int h = rr >> 2, g = rr & 3;
        int orow = g * Hsz + h;
        float v = (k < INsz) ? Wih0[(size_t)orow * INsz + k]
                             : Whh0[(size_t)orow * Hsz + (k - INsz)];
        g_W0[idx] = __float2half(v);
    }
    for (size_t idx = t0; idx < (size_t)2048 * K1T; idx += stride) {
        int rr = (int)(idx / K1T), k = (int)(idx - (size_t)rr * K1T);
        int h = rr >> 2, g = rr & 3;
        int orow = g * Hsz + h;
        float v = (k < Hsz) ? Wih1[(size_t)orow * Hsz + k]
                            : Whh1[(size_t)orow * Hsz + (k - Hsz)];
        g_W1[idx] = __float2half(v);
    }
    for (size_t idx = t0; idx < (size_t)INsz * KFT; idx += stride)
        g_Wf[idx] = __float2half(fcW[idx]);
    for (size_t idx = t0; idx < (size_t)OUTsz * KLT; idx += stride)
        g_Wl[idx] = __float2half(linW[idx]);
    for (size_t t = t0; t < 2048; t += stride) {
        int h = (int)(t >> 2), g = (int)(t & 3);
        int orow = g * Hsz + h;
        g_b0[t] = bih0[orow] + bhh0[orow];
        g_b1[t] = bih1[orow] + bhh1[orow];
    }
    for (size_t t = t0; t < INsz; t += stride) g_bfc[t] = fcb[t];
    for (size_t t = t0; t < OUTsz; t += stride) g_bln[t] = linb[t];
    const size_t BH = (size_t)Bsz * Hsz;
    for (size_t i = t0; i < BH; i += stride) {
        int b = (int)(i >> 9), h = (int)(i & 511);
        g_x0[0][(size_t)b * K0T + 256 + h] = __float2half(h0[i]);
        g_x1[0][(size_t)b * K1T + 512 + h] = __float2half(h0[BH + i]);
        g_c[0][i] = c0[i];
        g_c[1][i] = c0[BH + i];
    }
    for (size_t i = t0; i < (size_t)Bsz * INsz; i += stride) {
        int b = (int)(i >> 8), z = (int)(i & 255);
        g_x0[0][(size_t)b * K0T + z] = __float2half(z0[i]);
    }
}

// ---------------- host ----------------
extern "C" void kernel_launch(void* const* d_in, const int* in_sizes, int n_in,
                              void* d_out, int out_size)
{
    const float* z0   = (const float*)d_in[0];
    const float* h0   = (const float*)d_in[1];
    const float* c0   = (const float*)d_in[2];
    const float* Wih0 = (const float*)d_in[3];
    const float* Whh0 = (const float*)d_in[4];
    const float* bih0 = (const float*)d_in[5];
    const float* bhh0 = (const float*)d_in[6];
    const float* Wih1 = (const float*)d_in[7];
    const float* Whh1 = (const float*)d_in[8];
    const float* bih1 = (const float*)d_in[9];
    const float* bhh1 = (const float*)d_in[10];
    const float* fcW  = (const float*)d_in[11];
    const float* fcb  = (const float*)d_in[12];
    const float* linW = (const float*)d_in[13];
    const float* linb = (const float*)d_in[14];

    fp16 *zs, *Wl;
    float *bln;
    cudaGetSymbolAddress((void**)&zs,  g_zs);
    cudaGetSymbolAddress((void**)&Wl,  g_Wl);
    cudaGetSymbolAddress((void**)&bln, g_bln);

    cudaFuncSetAttribute(decoder_persistent,
                         cudaFuncAttributeMaxDynamicSharedMemorySize, SMEMSZ);
    cudaFuncSetAttribute(lin_kernel,
                         cudaFuncAttributeMaxDynamicSharedMemorySize, SMEMSZ);

    prologue_kernel<<<2048, 256>>>(z0, h0, c0, Wih0, Whh0, bih0, bhh0,
                                   Wih1, Whh1, bih1, bhh1, fcW, fcb, linW, linb);

    decoder_persistent<<<GRIDC, NTHR, SMEMSZ>>>();

    dim3 gfin((Tsz * Bsz) / 128, OUTsz / 128);  // (1024, 2)
    lin_kernel<<<gfin, NTHR, SMEMSZ>>>(
        zs, INsz, Wl, KLT, bln, (float*)d_out, OUTsz);
}